// round 13
// baseline (speedup 1.0000x reference)
#include <cuda_runtime.h>

// FlowNet2 Resample2d (kernel_size=1) bilinear warp — converged structure.
// input1: [B, C, H, W] float, input2 (flow): [B, 2, H, W] float
//
// Proven inner loop (R6, best of 12 variants): one thread per pixel, scalar
// gathers, channel loop unroll-4, 32 regs, 2048 threads/SM. Kernel is L1
// sector-return bound (~14 L1 cyc/warp-channel = 4 gathers x ~3.4 sectors
// + 1 store wf); measured floor ~105us, best ~125us ncu.
// Dead ends measured: LDG.64/LDG.128 gathers (sector bill per 4B slice),
// smem staging (LDS conflicts + instr bloat), lockstep barriers, stcg,
// unroll-8 (occupancy), dual channel streams (issue pressure), paired
// sequential tiles (temporal locality loss), carveout (neutral).
// Rejected by analysis: tex2Dgather (needs CUDA array = forbidden alloc),
// shuffle-based corner dedup (sectors, not lanes, are the cost).
// R13: 128-thread blocks (64x2 tiles, 16 blocks/SM) — same warp geometry,
// finer scheduling granularity, smaller per-block gather window, smoother
// wave tail.

#define BB 8
#define CC 32
#define HH 512
#define WW 512
#define HWSZ (HH * WW)   // 2^18

__global__ __launch_bounds__(128, 16)
void resample2d_kernel(const float* __restrict__ in1,
                       const float* __restrict__ flow,
                       float* __restrict__ out) {
    // Block tile: 64 px wide x 2 rows. Grid = 8 x-chunks * 256 y-chunks * 8 b.
    int blk = blockIdx.x;
    int x0 = (blk & 7) << 6;            // x-chunk * 64
    int y0 = ((blk >> 3) & 255) << 1;   // y-chunk * 2
    int b  = blk >> 11;                 // batch

    int w = x0 + (threadIdx.x & 63);
    int h = y0 + (threadIdx.x >> 6);
    int hw = (h << 9) | w;

    const float* fl = flow + ((size_t)b << 19); // b * 2 * HWSZ
    float dx = __ldg(fl + hw);
    float dy = __ldg(fl + HWSZ + hw);

    float xf = (float)w + dx;
    float yf = (float)h + dy;
    float x0f = floorf(xf);
    float y0f = floorf(yf);
    float alpha = xf - x0f;   // unclamped fractional weights
    float beta  = yf - y0f;

    int ix0 = (int)x0f;
    int iy0 = (int)y0f;
    int xL = min(max(ix0,     0), WW - 1);
    int xR = min(max(ix0 + 1, 0), WW - 1);
    int yT = min(max(iy0,     0), HH - 1);
    int yB = min(max(iy0 + 1, 0), HH - 1);

    float wTR = alpha * (1.0f - beta);
    float wBL = (1.0f - alpha) * beta;
    float wBR = alpha * beta;
    float wTL = 1.0f - wTR - wBL - wBR;

    const float* base = in1 + ((size_t)b << 23);   // b * C * HWSZ
    const float* pTL = base + ((yT << 9) + xL);
    const float* pTR = base + ((yT << 9) + xR);
    const float* pBL = base + ((yB << 9) + xL);
    const float* pBR = base + ((yB << 9) + xR);
    float* op = out + ((size_t)b << 23) + hw;

    #pragma unroll 4
    for (int c = 0; c < CC; c++) {
        int off = c << 18;   // c * HWSZ
        float v = wTL * __ldg(pTL + off)
                + wTR * __ldg(pTR + off)
                + wBL * __ldg(pBL + off)
                + wBR * __ldg(pBR + off);
        op[off] = v;
    }
}

extern "C" void kernel_launch(void* const* d_in, const int* in_sizes, int n_in,
                              void* d_out, int out_size) {
    const float* input1 = (const float*)d_in[0];
    const float* input2 = (const float*)d_in[1];
    float* out = (float*)d_out;

    const int blocks = 8 * 256 * BB;   // 16384 tiles of 64x2
    resample2d_kernel<<<blocks, 128>>>(input1, input2, out);
}

// round 14
// speedup vs baseline: 1.0089x; 1.0089x over previous
#include <cuda_runtime.h>

// FlowNet2 Resample2d (kernel_size=1) bilinear warp — converged structure.
// input1: [B, C, H, W] float, input2 (flow): [B, 2, H, W] float
//
// Proven optimum (R6, best of 13 variants): 64x4 pixel tiles, 256 threads,
// one thread per pixel, scalar gathers, channel loop unroll-4, 32 regs,
// 8 blocks/SM. L1 sector-return bound (~14 L1 cyc/warp-channel).
// Dead ends measured: LDG.64/128 gathers, smem staging, lockstep barriers,
// stcg, unroll-8, dual channel streams, paired sequential tiles, carveout,
// 32x8 and 64x2 tiles (both directions of tile aspect lose vertical reuse
// or L1 density).
// R14 micro-lever: ld.global.nc.L1::evict_last on the 4 gather loads — the
// gather window lines are multiply reused across resident warps/blocks
// (measured ~40% of gather sectors still refill from L2), so pinning them
// to the high-retention L1 ways should raise hit rate. Store and flow loads
// keep default priority. Zero instruction/register/occupancy cost.

#define BB 8
#define CC 32
#define HH 512
#define WW 512
#define HWSZ (HH * WW)   // 2^18

__device__ __forceinline__ float ldg_el(const float* p) {
    float v;
    asm volatile("ld.global.nc.L1::evict_last.f32 %0, [%1];"
                 : "=f"(v) : "l"(p));
    return v;
}

__global__ __launch_bounds__(256, 8)
void resample2d_kernel(const float* __restrict__ in1,
                       const float* __restrict__ flow,
                       float* __restrict__ out) {
    // Block tile: 64 px wide x 4 rows. Grid = 8 x-chunks * 128 y-chunks * 8 b.
    int blk = blockIdx.x;
    int x0 = (blk & 7) << 6;            // x-chunk * 64
    int y0 = ((blk >> 3) & 127) << 2;   // y-chunk * 4
    int b  = blk >> 10;                 // batch

    int w = x0 + (threadIdx.x & 63);
    int h = y0 + (threadIdx.x >> 6);
    int hw = (h << 9) | w;

    const float* fl = flow + ((size_t)b << 19); // b * 2 * HWSZ
    float dx = __ldg(fl + hw);
    float dy = __ldg(fl + HWSZ + hw);

    float xf = (float)w + dx;
    float yf = (float)h + dy;
    float x0f = floorf(xf);
    float y0f = floorf(yf);
    float alpha = xf - x0f;   // unclamped fractional weights
    float beta  = yf - y0f;

    int ix0 = (int)x0f;
    int iy0 = (int)y0f;
    int xL = min(max(ix0,     0), WW - 1);
    int xR = min(max(ix0 + 1, 0), WW - 1);
    int yT = min(max(iy0,     0), HH - 1);
    int yB = min(max(iy0 + 1, 0), HH - 1);

    float wTR = alpha * (1.0f - beta);
    float wBL = (1.0f - alpha) * beta;
    float wBR = alpha * beta;
    float wTL = 1.0f - wTR - wBL - wBR;

    const float* base = in1 + ((size_t)b << 23);   // b * C * HWSZ
    const float* pTL = base + ((yT << 9) + xL);
    const float* pTR = base + ((yT << 9) + xR);
    const float* pBL = base + ((yB << 9) + xL);
    const float* pBR = base + ((yB << 9) + xR);
    float* op = out + ((size_t)b << 23) + hw;

    #pragma unroll 4
    for (int c = 0; c < CC; c++) {
        int off = c << 18;   // c * HWSZ
        float v = wTL * ldg_el(pTL + off)
                + wTR * ldg_el(pTR + off)
                + wBL * ldg_el(pBL + off)
                + wBR * ldg_el(pBR + off);
        op[off] = v;
    }
}

extern "C" void kernel_launch(void* const* d_in, const int* in_sizes, int n_in,
                              void* d_out, int out_size) {
    const float* input1 = (const float*)d_in[0];
    const float* input2 = (const float*)d_in[1];
    float* out = (float*)d_out;

    const int blocks = 8 * 128 * BB;   // 8192 tiles of 64x4
    resample2d_kernel<<<blocks, 256>>>(input1, input2, out);
}